// round 1
// baseline (speedup 1.0000x reference)
#include <cuda_runtime.h>
#include <math.h>

#define NN 10000
#define EE 320000
#define UU 256

// ---------------- static device scratch (no allocations allowed) ----------------
__device__ float g_eA[EE * UU];   // edge features ping
__device__ float g_eB[EE * UU];   // edge features pong
__device__ float g_xA[NN * UU];   // node features ping
__device__ float g_xB[NN * UU];   // node features pong
__device__ float g_xW1[NN * UU];  // x@W1 + b1
__device__ float g_xW2[NN * UU];  // x@W2 + b2
__device__ float g_xWs[NN * UU];  // x@Ws
__device__ float g_xWt[NN * UU];  // x@Wt
__device__ float g_agg[NN * UU];  // scatter accumulator

// ---------------- small elementwise kernels ----------------

__global__ void zero_kernel(float4* __restrict__ p, int n4) {
    int i = blockIdx.x * blockDim.x + threadIdx.x;
    if (i < n4) p[i] = make_float4(0.f, 0.f, 0.f, 0.f);
}

// x[n,u] = pos[n,0]*Wp[0,u] + pos[n,1]*Wp[1,u] + bp[u]
__global__ void init_x_kernel(const float* __restrict__ pos, const float* __restrict__ Wp,
                              const float* __restrict__ bp, float* __restrict__ x) {
    int i = blockIdx.x * blockDim.x + threadIdx.x;   // over NN*64 float4 groups
    if (i >= NN * 64) return;
    int n = i >> 6, c = i & 63;
    float p0 = pos[n * 2 + 0], p1 = pos[n * 2 + 1];
    float4 w0 = ((const float4*)Wp)[c];
    float4 w1 = ((const float4*)Wp)[64 + c];
    float4 b  = ((const float4*)bp)[c];
    float4 r;
    r.x = p0 * w0.x + p1 * w1.x + b.x;
    r.y = p0 * w0.y + p1 * w1.y + b.y;
    r.z = p0 * w0.z + p1 * w1.z + b.z;
    r.w = p0 * w0.w + p1 * w1.w + b.w;
    ((float4*)x)[i] = r;
}

// e[m,u] = a[m]*Wa[u] + ba[u]
__global__ void init_e_kernel(const float* __restrict__ a, const float* __restrict__ Wa,
                              const float* __restrict__ ba, float* __restrict__ e) {
    int i = blockIdx.x * blockDim.x + threadIdx.x;   // over EE*64
    if (i >= EE * 64) return;
    int m = i >> 6, c = i & 63;
    float av = a[m];
    float4 w = ((const float4*)Wa)[c];
    float4 b = ((const float4*)ba)[c];
    float4 r;
    r.x = av * w.x + b.x;
    r.y = av * w.y + b.y;
    r.z = av * w.z + b.z;
    r.w = av * w.w + b.w;
    ((float4*)e)[i] = r;
}

// msg = sigmoid(e[m,:]) * xW2[src[m],:]; atomicAdd into agg[dst[m],:]
__global__ void scatter_kernel(const float* __restrict__ e, const float* __restrict__ xW2,
                               const int* __restrict__ src, const int* __restrict__ dst,
                               float* __restrict__ agg) {
    int i = blockIdx.x * blockDim.x + threadIdx.x;   // over EE*64
    if (i >= EE * 64) return;
    int m = i >> 6, c = i & 63;
    int s = src[m], d = dst[m];
    float4 ev = ((const float4*)e)[i];
    float4 wv = ((const float4*)xW2)[s * 64 + c];
    float4 g;
    g.x = wv.x / (1.f + __expf(-ev.x));
    g.y = wv.y / (1.f + __expf(-ev.y));
    g.z = wv.z / (1.f + __expf(-ev.z));
    g.w = wv.w / (1.f + __expf(-ev.w));
    float* ag = agg + d * 256 + c * 4;
    atomicAdd(ag + 0, g.x);
    atomicAdd(ag + 1, g.y);
    atomicAdd(ag + 2, g.z);
    atomicAdd(ag + 3, g.w);
}

// x_new = x + relu(xW1 + agg)    (xW1 already has b1)
__global__ void node_update_kernel(const float* __restrict__ x, const float* __restrict__ xW1,
                                   const float* __restrict__ agg, float* __restrict__ xo) {
    int i = blockIdx.x * blockDim.x + threadIdx.x;   // over NN*64
    if (i >= NN * 64) return;
    float4 xv = ((const float4*)x)[i];
    float4 wv = ((const float4*)xW1)[i];
    float4 av = ((const float4*)agg)[i];
    float4 r;
    r.x = xv.x + fmaxf(wv.x + av.x, 0.f);
    r.y = xv.y + fmaxf(wv.y + av.y, 0.f);
    r.z = xv.z + fmaxf(wv.z + av.z, 0.f);
    r.w = xv.w + fmaxf(wv.w + av.w, 0.f);
    ((float4*)xo)[i] = r;
}

// ---------------- generic tiled SGEMM (K=256 fixed) with fused epilogues ----------------
// mode 0: C[M,Nc] = A@B (+bias)
// mode 1: C = Ein + relu(A@B + gS[src] + gT[dst] + beL)     (Nc==256)
// mode 2: MLP head: h = A@B + ea*B[256,:] + bm1; prelu; out[m] = h . Wm2 + bm2  (Nc==128)
__global__ void __launch_bounds__(256)
gemm_kernel(const float* __restrict__ A, const float* __restrict__ B,
            const float* __restrict__ bias, float* __restrict__ C,
            int M, int Nc, int mode,
            const int* __restrict__ src, const int* __restrict__ dst,
            const float* __restrict__ gS, const float* __restrict__ gT,
            const float* __restrict__ beL, const float* __restrict__ Ein,
            const float* __restrict__ ea, const float* __restrict__ bm1,
            const float* __restrict__ alpha, const float* __restrict__ Wm2,
            const float* __restrict__ bm2) {
    __shared__ float As[8][128];
    __shared__ float Bs[8][128];

    int tid = threadIdx.x;
    int tx = tid & 15, ty = tid >> 4;
    int row0 = blockIdx.x * 128;
    int col0 = blockIdx.y * 128;

    int aRow = tid >> 1;          // 0..127
    int aK   = (tid & 1) * 4;     // 0 or 4
    int bK   = tid >> 5;          // 0..7
    int bCol = (tid & 31) * 4;    // 0..124

    float acc[8][8];
#pragma unroll
    for (int i = 0; i < 8; i++)
#pragma unroll
        for (int j = 0; j < 8; j++) acc[i][j] = 0.f;

    for (int k0 = 0; k0 < 256; k0 += 8) {
        int gRow = row0 + aRow;
        float4 av = make_float4(0.f, 0.f, 0.f, 0.f);
        if (gRow < M) av = *(const float4*)&A[gRow * 256 + k0 + aK];
        As[aK + 0][aRow] = av.x;
        As[aK + 1][aRow] = av.y;
        As[aK + 2][aRow] = av.z;
        As[aK + 3][aRow] = av.w;

        float4 bv = *(const float4*)&B[(k0 + bK) * Nc + col0 + bCol];
        *(float4*)&Bs[bK][bCol] = bv;
        __syncthreads();

#pragma unroll
        for (int kk = 0; kk < 8; kk++) {
            float a[8], b[8];
#pragma unroll
            for (int i = 0; i < 8; i++) a[i] = As[kk][ty * 8 + i];
#pragma unroll
            for (int j = 0; j < 8; j++) b[j] = Bs[kk][tx * 8 + j];
#pragma unroll
            for (int i = 0; i < 8; i++)
#pragma unroll
                for (int j = 0; j < 8; j++) acc[i][j] += a[i] * b[j];
        }
        __syncthreads();
    }

    if (mode == 0) {
#pragma unroll
        for (int i = 0; i < 8; i++) {
            int m = row0 + ty * 8 + i;
            if (m >= M) continue;
#pragma unroll
            for (int j4 = 0; j4 < 2; j4++) {
                int n = col0 + tx * 8 + j4 * 4;
                float4 v;
                v.x = acc[i][j4 * 4 + 0];
                v.y = acc[i][j4 * 4 + 1];
                v.z = acc[i][j4 * 4 + 2];
                v.w = acc[i][j4 * 4 + 3];
                if (bias) {
                    float4 b4 = *(const float4*)&bias[n];
                    v.x += b4.x; v.y += b4.y; v.z += b4.z; v.w += b4.w;
                }
                *(float4*)&C[m * Nc + n] = v;
            }
        }
    } else if (mode == 1) {
#pragma unroll
        for (int i = 0; i < 8; i++) {
            int m = row0 + ty * 8 + i;
            if (m >= M) continue;
            int s = src[m], d = dst[m];
            const float* gSr = gS + s * 256;
            const float* gTr = gT + d * 256;
#pragma unroll
            for (int j4 = 0; j4 < 2; j4++) {
                int n = col0 + tx * 8 + j4 * 4;
                float4 gs = *(const float4*)&gSr[n];
                float4 gt = *(const float4*)&gTr[n];
                float4 be4 = *(const float4*)&beL[n];
                float4 ei = *(const float4*)&Ein[m * 256 + n];
                float4 v;
                v.x = ei.x + fmaxf(acc[i][j4 * 4 + 0] + gs.x + gt.x + be4.x, 0.f);
                v.y = ei.y + fmaxf(acc[i][j4 * 4 + 1] + gs.y + gt.y + be4.y, 0.f);
                v.z = ei.z + fmaxf(acc[i][j4 * 4 + 2] + gs.z + gt.z + be4.z, 0.f);
                v.w = ei.w + fmaxf(acc[i][j4 * 4 + 3] + gs.w + gt.w + be4.w, 0.f);
                *(float4*)&C[m * 256 + n] = v;
            }
        }
    } else {  // mode 2: MLP head, Nc == 128, col0 == 0
        float alpha0 = alpha[0];
        float bm20 = bm2[0];
#pragma unroll
        for (int i = 0; i < 8; i++) {
            int m = row0 + ty * 8 + i;
            float partial = 0.f;
            if (m < M) {
                float am = ea[m];
#pragma unroll
                for (int j = 0; j < 8; j++) {
                    int n = tx * 8 + j;
                    float h = acc[i][j] + am * B[256 * 128 + n] + bm1[n];
                    h = (h > 0.f) ? h : alpha0 * h;
                    partial += h * Wm2[n];
                }
            }
            // reduce over 16-lane group (tx)
            partial += __shfl_xor_sync(0xffffffffu, partial, 8);
            partial += __shfl_xor_sync(0xffffffffu, partial, 4);
            partial += __shfl_xor_sync(0xffffffffu, partial, 2);
            partial += __shfl_xor_sync(0xffffffffu, partial, 1);
            if (tx == 0 && m < M) C[m] = partial + bm20;
        }
    }
}

// ---------------- launch ----------------

static void launch_gemm(const float* A, const float* B, const float* bias, float* C,
                        int M, int Nc, int mode,
                        const int* src = nullptr, const int* dst = nullptr,
                        const float* gS = nullptr, const float* gT = nullptr,
                        const float* beL = nullptr, const float* Ein = nullptr,
                        const float* ea = nullptr, const float* bm1 = nullptr,
                        const float* alpha = nullptr, const float* Wm2 = nullptr,
                        const float* bm2 = nullptr) {
    dim3 grid((M + 127) / 128, Nc / 128);
    gemm_kernel<<<grid, 256>>>(A, B, bias, C, M, Nc, mode, src, dst, gS, gT, beL,
                               Ein, ea, bm1, alpha, Wm2, bm2);
}

extern "C" void kernel_launch(void* const* d_in, const int* in_sizes, int n_in,
                              void* d_out, int out_size) {
    const float* pos  = (const float*)d_in[0];
    const float* ea   = (const float*)d_in[1];
    const int*   ei   = (const int*)d_in[2];
    const float* Wp   = (const float*)d_in[3];
    const float* bp   = (const float*)d_in[4];
    const float* Wa   = (const float*)d_in[5];
    const float* ba   = (const float*)d_in[6];
    const float* W1   = (const float*)d_in[7];
    const float* b1   = (const float*)d_in[8];
    const float* W2   = (const float*)d_in[9];
    const float* b2   = (const float*)d_in[10];
    const float* We   = (const float*)d_in[11];
    const float* be   = (const float*)d_in[12];
    const float* Ws   = (const float*)d_in[13];
    const float* Wt   = (const float*)d_in[14];
    const float* Wm1  = (const float*)d_in[15];
    const float* bm1  = (const float*)d_in[16];
    const float* alpha = (const float*)d_in[17];
    const float* Wm2  = (const float*)d_in[18];
    const float* bm2  = (const float*)d_in[19];
    float* out = (float*)d_out;

    const int* src = ei;
    const int* dst = ei + EE;

    float *eA, *eB, *xA, *xB, *xw1, *xw2, *xws, *xwt, *agg;
    cudaGetSymbolAddress((void**)&eA,  g_eA);
    cudaGetSymbolAddress((void**)&eB,  g_eB);
    cudaGetSymbolAddress((void**)&xA,  g_xA);
    cudaGetSymbolAddress((void**)&xB,  g_xB);
    cudaGetSymbolAddress((void**)&xw1, g_xW1);
    cudaGetSymbolAddress((void**)&xw2, g_xW2);
    cudaGetSymbolAddress((void**)&xws, g_xWs);
    cudaGetSymbolAddress((void**)&xwt, g_xWt);
    cudaGetSymbolAddress((void**)&agg, g_agg);

    const int TB = 256;

    // init
    init_x_kernel<<<(NN * 64 + TB - 1) / TB, TB>>>(pos, Wp, bp, xA);
    init_e_kernel<<<(EE * 64 + TB - 1) / TB, TB>>>(ea, Wa, ba, eA);

    float* xcur = xA;
    float* xnxt = xB;
    float* ecur = eA;
    float* enxt = eB;

    for (int l = 0; l < 3; l++) {
        const float* W1l = W1 + l * 65536;
        const float* W2l = W2 + l * 65536;
        const float* Wsl = Ws + l * 65536;
        const float* Wtl = Wt + l * 65536;
        const float* Wel = We + l * 65536;
        const float* b1l = b1 + l * 256;
        const float* b2l = b2 + l * 256;
        const float* bel = be + l * 256;

        // node-side GEMMs (all from old x)
        launch_gemm(xcur, W1l, b1l, xw1, NN, 256, 0);
        launch_gemm(xcur, W2l, b2l, xw2, NN, 256, 0);
        launch_gemm(xcur, Wsl, nullptr, xws, NN, 256, 0);
        launch_gemm(xcur, Wtl, nullptr, xwt, NN, 256, 0);

        // gated scatter: agg = segment_sum(sigmoid(e) * xW2[src], dst)
        zero_kernel<<<(NN * 64 + TB - 1) / TB, TB>>>((float4*)agg, NN * 64);
        scatter_kernel<<<(EE * 64 + TB - 1) / TB, TB>>>(ecur, xw2, src, dst, agg);

        // fused edge update: e_new = e + relu(e@We + xWs[src] + xWt[dst] + be)
        launch_gemm(ecur, Wel, nullptr, enxt, EE, 256, 1,
                    src, dst, xws, xwt, bel, ecur);

        // node update: x_new = x + relu(xW1 + agg)
        node_update_kernel<<<(NN * 64 + TB - 1) / TB, TB>>>(xcur, xw1, agg, xnxt);

        { float* t = xcur; xcur = xnxt; xnxt = t; }
        { float* t = ecur; ecur = enxt; enxt = t; }
    }

    // final edge update (l = 3)
    launch_gemm(xcur, Ws + 3 * 65536, nullptr, xws, NN, 256, 0);
    launch_gemm(xcur, Wt + 3 * 65536, nullptr, xwt, NN, 256, 0);
    launch_gemm(ecur, We + 3 * 65536, nullptr, enxt, EE, 256, 1,
                src, dst, xws, xwt, be + 3 * 256, ecur);
    { float* t = ecur; ecur = enxt; enxt = t; }

    // fused MLP head: out = prelu([e | ea] @ Wm1 + bm1) @ Wm2 + bm2
    launch_gemm(ecur, Wm1, nullptr, out, EE, 128, 2,
                nullptr, nullptr, nullptr, nullptr, nullptr, nullptr,
                ea, bm1, alpha, Wm2, bm2);

    (void)in_sizes; (void)n_in; (void)out_size;
}